// round 12
// baseline (speedup 1.0000x reference)
#include <cuda_runtime.h>

#define BB 32
#define NN 784
#define CC 256
#define FF 1024
#define MM (BB*NN)      // 25088
#define HEADS 8
#define DIMH 32

typedef unsigned long long u64;

// ---- f32x2 packed-math helpers ----
__device__ __forceinline__ u64 pk2(float lo, float hi) {
    u64 r; asm("mov.b64 %0,{%1,%2};" : "=l"(r) : "f"(lo), "f"(hi)); return r;
}
__device__ __forceinline__ void upk2(u64 v, float& lo, float& hi) {
    asm("mov.b64 {%0,%1},%2;" : "=f"(lo), "=f"(hi) : "l"(v));
}
__device__ __forceinline__ void fma2(u64& d, u64 a, u64 b) {
    asm("fma.rn.f32x2 %0,%1,%2,%3;" : "=l"(d) : "l"(a), "l"(b), "l"(d));
}

// ---------------- scratch ----------------
__device__ float g_x[(size_t)MM * FF];
__device__ float g_attn[(size_t)MM * 512];
__device__ float g_sum[FF];
__device__ float g_sumsq[FF];
__device__ float g_affa[FF];
__device__ float g_affb[FF];

__global__ void zero_stats_kernel() {
    int i = blockIdx.x * blockDim.x + threadIdx.x;
    if (i < FF) { g_sum[i] = 0.f; g_sumsq[i] = 0.f; }
}

// ---------------- SGEMM: 128x128 block, 8x8 micro (split +-64) — r11 validated ----------------
template<int KTOT, int LDA, int LDB, int LDC, bool STATS>
__global__ __launch_bounds__(256, 2) void sgemm_kernel(
    const float* __restrict__ A, const float* __restrict__ Bm, float* __restrict__ C)
{
    __shared__ __align__(16) float As[16][128];
    __shared__ __align__(16) float Bs[16][128];
    __shared__ float csum[128], csq[128];

    const int m0 = blockIdx.y * 128;
    const int n0 = blockIdx.x * 128;
    const int tid = threadIdx.x;
    const int tx = tid & 15, ty = tid >> 4;
    const int tx4 = tx * 4, ty4 = ty * 4;

    float acc[8][8] = {};

    for (int k0 = 0; k0 < KTOT; k0 += 16) {
        #pragma unroll
        for (int r = 0; r < 2; r++) {
            int f4 = tid + r * 256;
            int m = f4 >> 2, kq = f4 & 3;
            float4 v = *reinterpret_cast<const float4*>(&A[(size_t)(m0 + m) * LDA + k0 + kq * 4]);
            As[kq*4+0][m] = v.x; As[kq*4+1][m] = v.y; As[kq*4+2][m] = v.z; As[kq*4+3][m] = v.w;
        }
        #pragma unroll
        for (int r = 0; r < 2; r++) {
            int f4 = tid + r * 256;
            int k = f4 >> 5, n4 = f4 & 31;
            float4 v = *reinterpret_cast<const float4*>(&Bm[(size_t)(k0 + k) * LDB + n0 + n4 * 4]);
            *reinterpret_cast<float4*>(&Bs[k][n4 * 4]) = v;
        }
        __syncthreads();
        #pragma unroll
        for (int k = 0; k < 16; k++) {
            float4 a0 = *reinterpret_cast<const float4*>(&As[k][ty4]);
            float4 a1 = *reinterpret_cast<const float4*>(&As[k][64 + ty4]);
            float4 b0 = *reinterpret_cast<const float4*>(&Bs[k][tx4]);
            float4 b1 = *reinterpret_cast<const float4*>(&Bs[k][64 + tx4]);
            float av[8] = {a0.x, a0.y, a0.z, a0.w, a1.x, a1.y, a1.z, a1.w};
            float bv[8] = {b0.x, b0.y, b0.z, b0.w, b1.x, b1.y, b1.z, b1.w};
            #pragma unroll
            for (int i = 0; i < 8; i++)
                #pragma unroll
                for (int j = 0; j < 8; j++)
                    acc[i][j] = fmaf(av[i], bv[j], acc[i][j]);
        }
        __syncthreads();
    }

    #pragma unroll
    for (int i = 0; i < 8; i++) {
        int row = m0 + ((i < 4) ? (ty4 + i) : (64 + ty4 + i - 4));
        *reinterpret_cast<float4*>(&C[(size_t)row * LDC + n0 + tx4]) =
            make_float4(acc[i][0], acc[i][1], acc[i][2], acc[i][3]);
        *reinterpret_cast<float4*>(&C[(size_t)row * LDC + n0 + 64 + tx4]) =
            make_float4(acc[i][4], acc[i][5], acc[i][6], acc[i][7]);
    }

    if (STATS) {
        if (tid < 128) { csum[tid] = 0.f; csq[tid] = 0.f; }
        __syncthreads();
        #pragma unroll
        for (int j = 0; j < 8; j++) {
            int col = (j < 4) ? (tx4 + j) : (64 + tx4 + j - 4);
            float s = 0.f, sq = 0.f;
            #pragma unroll
            for (int i = 0; i < 8; i++) { float v = acc[i][j]; s += v; sq = fmaf(v, v, sq); }
            atomicAdd(&csum[col], s);
            atomicAdd(&csq[col], sq);
        }
        __syncthreads();
        if (tid < 128) {
            atomicAdd(&g_sum[n0 + tid], csum[tid]);
            atomicAdd(&g_sumsq[n0 + tid], csq[tid]);
        }
    }
}

// ---------------- BN finalize ----------------
__global__ void bn_finalize_kernel(const float* __restrict__ bn_scale) {
    int f = blockIdx.x * blockDim.x + threadIdx.x;
    if (f < FF) {
        float mean = g_sum[f] * (1.f / MM);
        float var  = g_sumsq[f] * (1.f / MM) - mean * mean;
        float r = rsqrtf(var + 1e-5f);
        float a = r * bn_scale[f];
        g_affa[f] = a;
        g_affb[f] = -mean * a;
    }
}

// ---------------- fused flash attention: QT=112, KT=64, 224 threads ----------------
// Lane decomposition for 16 q-rows/warp: tx = tid&7 (k / vd), ty = tid>>3 (0..27, 4 q each).
// Warp = 4 ty x 8 tx. Thread tile: S 4q x 8k (two 4-col halves), PV 4q x 8vd (f32x2).
// Layout/conflict design:
//   Qs [112][32], float4-group swizzled by (q>>2)&7  -> S-phase Q reads: 4 distinct slots, 1 wf
//   Ks [64][32],  float4-group swizzled by (k>>2)&7  -> K reads 1 wf (both k-halves: group == tx)
//   Vs [64][64] plain                                 -> V reads 1 wf (8 tx distinct slots)
//   Ss [112][64], col-group swizzled by (q>>2)&7      -> S stores 4 wf, PV P reads 1 wf
// Fixed-shift softmax p = exp(s + bias - 20); l via tx == (kk&7); 8-lane shfl reduce.
#define EXP_SHIFT 20.0f
#define AT_SMEM_FLOATS (112*32 + 64*32 + 64*64 + 112*64 + 256)
__global__ __launch_bounds__(224, 2) void attention_kernel(
    const float* __restrict__ bias, float* __restrict__ out)
{
    extern __shared__ __align__(16) float sm[];
    float* Qs = sm;                 // 3584
    float* Ks = sm + 3584;          // 2048
    float* Vs = sm + 5632;          // 4096
    float* Ss = sm + 9728;          // 7168 (112*64)
    float* cA = sm + 16896;         // 128
    float* cB = sm + 17024;         // 128

    const int tid = threadIdx.x;
    const int tx = tid & 7, ty = tid >> 3;     // ty 0..27
    const int tx4 = tx * 4, ty4 = ty * 4;
    const int tyg = ty & 7;                    // (q>>2)&7 for q = ty4+i (i<4)
    const int q0 = blockIdx.x * 112;
    const int h  = blockIdx.y;
    const int b  = blockIdx.z;

    if (tid < 128) {
        int seg = tid >> 5, d = tid & 31;
        int f = seg * 256 + h * 32 + d;
        cA[tid] = g_affa[f];
        cB[tid] = g_affb[f];
    }
    __syncthreads();

    // Q tile [112,32], normalized, group-swizzled by (q>>2)&7 (784 = 7*112 -> no q mask)
    for (int idx = tid; idx < 112 * 32; idx += 224) {
        int q = idx >> 5, d = idx & 31;
        float v = fmaf(g_x[(size_t)(b * NN + q0 + q) * FF + h * 32 + d], cA[d], cB[d]);
        Qs[q * 32 + ((((d >> 2) ^ ((q >> 2) & 7)) << 2) | (d & 3))] = v;
    }

    u64 acc2[4][4] = {};   // [i][vd pairs: {tx4,+1},{+2,+3},{32+tx4,+1},{+2,+3}]
    float lacc[4] = {0.f, 0.f, 0.f, 0.f};

    for (int kc = 0; kc < 13; kc++) {
        const int k0 = kc * 64;
        __syncthreads();   // protect Ks/Vs/Ss from previous-iteration consumers

        // K chunk [64,32], XOR-swizzled float4 groups (r7 pattern)
        for (int idx = tid; idx < 64 * 32; idx += 224) {
            int k = idx >> 5, d = idx & 31;
            int row = k0 + k;
            float v = (row < NN) ? fmaf(g_x[(size_t)(b * NN + row) * FF + 256 + h * 32 + d],
                                        cA[32 + d], cB[32 + d]) : 0.f;
            Ks[k * 32 + ((((d >> 2) ^ ((k >> 2) & 7)) << 2) | (d & 3))] = v;
        }
        // V chunk [64,64] (v1 | v2), plain
        for (int idx = tid; idx < 64 * 64; idx += 224) {
            int k = idx >> 6, d = idx & 63;
            int row = k0 + k;
            int col = 512 + ((d >> 5) << 8) + h * 32 + (d & 31);
            float v = (row < NN) ? fmaf(g_x[(size_t)(b * NN + row) * FF + col],
                                        cA[64 + d], cB[64 + d]) : 0.f;
            Vs[k * 64 + d] = v;
        }
        __syncthreads();

        // ---- S = Q K^T: 4q x 8k scalar (s[4][8]), Q hoisted per dq ----
        {
            float s[4][8] = {};
            #pragma unroll
            for (int dq = 0; dq < 8; dq++) {
                float4 qa[4];
                #pragma unroll
                for (int i = 0; i < 4; i++)
                    qa[i] = *reinterpret_cast<const float4*>(
                        &Qs[(ty4 + i) * 32 + ((dq ^ tyg) << 2)]);
                #pragma unroll
                for (int jh = 0; jh < 2; jh++) {
                    float4 kb[4];
                    #pragma unroll
                    for (int j = 0; j < 4; j++)
                        kb[j] = *reinterpret_cast<const float4*>(
                            &Ks[(jh * 32 + tx4 + j) * 32 + ((dq ^ tx) << 2)]);
                    #pragma unroll
                    for (int i = 0; i < 4; i++)
                        #pragma unroll
                        for (int j = 0; j < 4; j++) {
                            float acc = s[i][jh * 4 + j];
                            acc = fmaf(qa[i].x, kb[j].x, acc);
                            acc = fmaf(qa[i].y, kb[j].y, acc);
                            acc = fmaf(qa[i].z, kb[j].z, acc);
                            acc = fmaf(qa[i].w, kb[j].w, acc);
                            s[i][jh * 4 + j] = acc;
                        }
                }
            }
            // exp + bias, store to Ss (col-group swizzled by tyg)
            #pragma unroll
            for (int jh = 0; jh < 2; jh++) {
                const bool kvalid = (k0 + jh * 32 + tx4 + 3) < NN;   // 784 % 4 == 0
                const int c4 = (jh << 3) | ((tx ^ tyg) & 7);          // swizzled group
                #pragma unroll
                for (int i = 0; i < 4; i++) {
                    int q = ty4 + i;
                    float4 o;
                    if (kvalid) {
                        float4 bi = *reinterpret_cast<const float4*>(
                            &bias[(size_t)(q0 + q) * NN + k0 + jh * 32 + tx4]);
                        o.x = __expf(s[i][jh*4+0] + bi.x - EXP_SHIFT);
                        o.y = __expf(s[i][jh*4+1] + bi.y - EXP_SHIFT);
                        o.z = __expf(s[i][jh*4+2] + bi.z - EXP_SHIFT);
                        o.w = __expf(s[i][jh*4+3] + bi.w - EXP_SHIFT);
                    } else {
                        o = make_float4(0.f, 0.f, 0.f, 0.f);
                    }
                    *reinterpret_cast<float4*>(&Ss[q * 64 + (c4 << 2)]) = o;
                }
            }
        }
        __syncthreads();

        // ---- PV accumulate: 4q x 8vd f32x2 + free l accumulation ----
        #pragma unroll
        for (int kk = 0; kk < 16; kk++) {
            const int rc4 = (kk & 8) | ((kk ^ tyg) & 7);   // swizzled read group
            float4 P[4];
            #pragma unroll
            for (int i = 0; i < 4; i++)
                P[i] = *reinterpret_cast<const float4*>(&Ss[(ty4 + i) * 64 + (rc4 << 2)]);
            if (tx == (kk & 7)) {   // each kk-slice counted exactly once across tx
                #pragma unroll
                for (int i = 0; i < 4; i++)
                    lacc[i] += (P[i].x + P[i].y) + (P[i].z + P[i].w);
            }
            #pragma unroll
            for (int c = 0; c < 4; c++) {
                int k = kk * 4 + c;
                ulonglong2 v0 = *reinterpret_cast<const ulonglong2*>(&Vs[k * 64 + tx4]);
                ulonglong2 v1 = *reinterpret_cast<const ulonglong2*>(&Vs[k * 64 + 32 + tx4]);
                #pragma unroll
                for (int i = 0; i < 4; i++) {
                    float p = (c == 0) ? P[i].x : (c == 1) ? P[i].y : (c == 2) ? P[i].z : P[i].w;
                    u64 pp = pk2(p, p);
                    fma2(acc2[i][0], pp, v0.x);
                    fma2(acc2[i][1], pp, v0.y);
                    fma2(acc2[i][2], pp, v1.x);
                    fma2(acc2[i][3], pp, v1.y);
                }
            }
        }
    }

    // ---- reduce l across the 8-lane tx group ----
    #pragma unroll
    for (int i = 0; i < 4; i++) {
        #pragma unroll
        for (int d = 1; d < 8; d <<= 1)
            lacc[i] += __shfl_xor_sync(0xffffffffu, lacc[i], d);
    }

    // ---- epilogue: /l, hard_swish, write [ (b*N+q), h*64 + {tx4, 32+tx4} ] ----
    #pragma unroll
    for (int i = 0; i < 4; i++) {
        int q = ty4 + i;
        float inv = 1.0f / lacc[i];
        float v[8];
        upk2(acc2[i][0], v[0], v[1]);
        upk2(acc2[i][1], v[2], v[3]);
        upk2(acc2[i][2], v[4], v[5]);
        upk2(acc2[i][3], v[6], v[7]);
        #pragma unroll
        for (int j = 0; j < 8; j++) {
            v[j] *= inv;
            v[j] = v[j] * __saturatef((v[j] + 3.0f) * (1.0f / 6.0f));
        }
        float* op = &out[((size_t)(b * NN + q0 + q)) * 512 + h * 64];
        *reinterpret_cast<float4*>(op + tx4)      = make_float4(v[0], v[1], v[2], v[3]);
        *reinterpret_cast<float4*>(op + 32 + tx4) = make_float4(v[4], v[5], v[6], v[7]);
    }
}

// ---------------- launch ----------------
extern "C" void kernel_launch(void* const* d_in, const int* in_sizes, int n_in,
                              void* d_out, int out_size) {
    const float* inputs    = (const float*)d_in[0];
    const float* w_qkv     = (const float*)d_in[1];
    const float* bn_scale  = (const float*)d_in[2];
    const float* attn_bias = (const float*)d_in[3];
    const float* w_out     = (const float*)d_in[4];
    float* out = (float*)d_out;

    float *px, *pattn;
    cudaGetSymbolAddress((void**)&px, g_x);
    cudaGetSymbolAddress((void**)&pattn, g_attn);

    const int at_smem = AT_SMEM_FLOATS * 4;   // 68608 bytes
    cudaFuncSetAttribute(attention_kernel,
                         cudaFuncAttributeMaxDynamicSharedMemorySize, at_smem);

    zero_stats_kernel<<<4, 256>>>();
    sgemm_kernel<256, 256, 1024, 1024, true><<<dim3(8, 196), 256>>>(inputs, w_qkv, px);
    bn_finalize_kernel<<<4, 256>>>(bn_scale);
    attention_kernel<<<dim3(7, HEADS, BB), 224, at_smem>>>(attn_bias, pattn);
    sgemm_kernel<512, 512, 256, 256, false><<<dim3(2, 196), 256>>>(pattn, w_out, out);
}